// round 16
// baseline (speedup 1.0000x reference)
#include <cuda_runtime.h>
#include <cuda_fp16.h>
#include <math.h>
#include <stdint.h>

typedef __half f16;

// Problem dims (fixed)
#define NND   1024
#define HR1D  2048
#define HR2D  4096
#define H1D   4
#define H2D   8
#define CDD   512

// GEMM tiling: CTA 128(M) x 256(N), BK=64, single-pass fp16, 8 warps of 64x64
#define BK    64
#define LDS   72                       // smem row stride in f16 (padded)
#define TA_B  (128 * LDS * 2)          // 18432
#define TB_B  (256 * LDS * 2)          // 36864
#define STAGE_B (TA_B + TB_B)          // 55296
#define NSTAGE 3
#define SMEM_TOTAL (NSTAGE * STAGE_B)  // 165888

// ---------------- scratch ----------------
__device__ float g_xT [NND * NND];
__device__ f16   g_xh [NND * NND];
__device__ f16   g_WTh[4 * HR2D * HR1D];
__device__ f16   g_Qh [NND * HR2D];
__device__ f16   g_Kh [NND * HR2D];
__device__ f16   g_Vth[HR2D * NND];
__device__ float g_S  [H2D * NND * NND];
__device__ f16   g_Sh [H2D * NND * NND];
__device__ float g_h1 [NND * HR1D];
__device__ f16   g_h1h[NND * HR1D];
__device__ float g_h2 [NND * HR2D];
__device__ float g_gg [NND * H2D];
__device__ float g_gna[HR2D];
__device__ float g_gnb[HR2D];

// ---------------- helpers ----------------
__device__ __forceinline__ uint32_t cvta_smem(const void* p) {
    uint32_t a;
    asm("{ .reg .u64 t; cvta.to.shared.u64 t, %1; cvt.u32.u64 %0, t; }" : "=r"(a) : "l"(p));
    return a;
}

__device__ __forceinline__ void ldm4(uint32_t addr, uint32_t& r0, uint32_t& r1,
                                     uint32_t& r2, uint32_t& r3) {
    asm volatile("ldmatrix.sync.aligned.m8n8.x4.shared.b16 {%0,%1,%2,%3}, [%4];"
                 : "=r"(r0), "=r"(r1), "=r"(r2), "=r"(r3) : "r"(addr));
}

__device__ __forceinline__ void mma16816(float* c, const uint32_t* a,
                                         uint32_t b0, uint32_t b1) {
    asm volatile(
        "mma.sync.aligned.m16n8k16.row.col.f32.f16.f16.f32 "
        "{%0,%1,%2,%3}, {%4,%5,%6,%7}, {%8,%9}, {%0,%1,%2,%3};"
        : "+f"(c[0]), "+f"(c[1]), "+f"(c[2]), "+f"(c[3])
        : "r"(a[0]), "r"(a[1]), "r"(a[2]), "r"(a[3]), "r"(b0), "r"(b1));
}

// shared GEMM core (row stride = K for both operands), single-pass fp16,
// CTA 128x256, 8 warps of 64x64.
struct Core {
    uint32_t sb;
    const f16 *Ah, *Bh;
    int K;
    int tid, lane, wid, m0, n0;
    float acc[4][8][4];

    __device__ __forceinline__ void init(uint32_t sb_, const f16* Ah_,
                                         const f16* Bh_, int K_) {
        sb = sb_; Ah = Ah_; Bh = Bh_; K = K_;
        tid = threadIdx.x; lane = tid & 31; wid = tid >> 5;
        m0 = (wid & 1) * 64; n0 = (wid >> 1) * 64;
        #pragma unroll
        for (int i = 0; i < 4; i++)
            #pragma unroll
            for (int j = 0; j < 8; j++)
                #pragma unroll
                for (int q = 0; q < 4; q++) acc[i][j][q] = 0.0f;
    }

    __device__ __forceinline__ void load_chunk(int ch, int s) {
        int k0 = ch * BK;
        uint32_t stb = sb + (uint32_t)s * STAGE_B;
        #pragma unroll
        for (int it = 0; it < 4; ++it) {
            int e = tid + it * 256;
            int r = e >> 3, c8 = (e & 7) * 8;
            const void* src = Ah + (long)r * K + k0 + c8;
            uint32_t dst = stb + (uint32_t)(r * LDS + c8) * 2;
            asm volatile("cp.async.cg.shared.global [%0], [%1], 16;"
                         :: "r"(dst), "l"(src));
        }
        #pragma unroll
        for (int it = 0; it < 8; ++it) {
            int e = tid + it * 256;
            int r = e >> 3, c8 = (e & 7) * 8;
            const void* src = Bh + (long)r * K + k0 + c8;
            uint32_t dst = stb + TA_B + (uint32_t)(r * LDS + c8) * 2;
            asm volatile("cp.async.cg.shared.global [%0], [%1], 16;"
                         :: "r"(dst), "l"(src));
        }
        asm volatile("cp.async.commit_group;");
    }

    __device__ __forceinline__ void compute(int s) {
        int arow = lane & 15, acol = (lane >> 4) * 8;
        int brow = (lane & 7) + ((lane >> 4) << 3);
        int bcol = ((lane >> 3) & 1) * 8;
        uint32_t stb = sb + (uint32_t)s * STAGE_B;
        #pragma unroll
        for (int ks = 0; ks < 4; ++ks) {
            int kk = ks * 16;
            uint32_t a[4][4];
            #pragma unroll
            for (int i = 0; i < 4; ++i)
                ldm4(stb + (uint32_t)((m0 + i * 16 + arow) * LDS + kk + acol) * 2,
                     a[i][0], a[i][1], a[i][2], a[i][3]);
            uint32_t b[8][2];
            #pragma unroll
            for (int jj = 0; jj < 4; ++jj) {
                uint32_t r0, r1, r2, r3;
                ldm4(stb + TA_B + (uint32_t)((n0 + jj * 16 + brow) * LDS + kk + bcol) * 2,
                     r0, r1, r2, r3);
                b[jj * 2][0] = r0;     b[jj * 2][1] = r1;
                b[jj * 2 + 1][0] = r2; b[jj * 2 + 1][1] = r3;
            }
            #pragma unroll
            for (int i = 0; i < 4; ++i)
                #pragma unroll
                for (int j = 0; j < 8; ++j)
                    mma16816(acc[i][j], a[i], b[j][0], b[j][1]);
        }
    }

    __device__ __forceinline__ void run() {
        int nch = K / BK;
        load_chunk(0, 0);
        load_chunk(1, 1);
        for (int ch = 0; ch < nch; ++ch) {
            if (ch + 1 < nch) asm volatile("cp.async.wait_group 1;" ::: "memory");
            else              asm volatile("cp.async.wait_group 0;" ::: "memory");
            __syncthreads();
            if (ch + 2 < nch) load_chunk(ch + 2, (ch + 2) % NSTAGE);
            compute(ch % NSTAGE);
        }
    }
};

// ---------------- fused multi-GEMM projection kernel ----------------
struct PJP {
    const f16* actH;           // [1024 x K]
    const f16* WTh;            // [4*Nd x K]
    f16 *Qh, *Kh, *Vth;
    float* hF;                 // skip fp32 [1024 x Nd]
    const float *qb, *kb, *sb, *vb;
    int K, Nd, tn0, tilesP;    // tn0 = 3*Nd/256, tilesP = 8*tn0
};

__global__ __launch_bounds__(256, 1) void proj_gemm(PJP p) {
    extern __shared__ char dsm[];
    uint32_t sb = cvta_smem(dsm);
    int t = blockIdx.x;

    const f16 *Ah, *Bh;
    f16* Oh = nullptr;
    float* Of = nullptr;
    const float* bias;
    int mode, obm, obn, ldc;
    if (t < p.tilesP) {
        int tm = t / p.tn0, tn = t % p.tn0;
        int bm = tm * 128, bn = tn * 256;
        Ah = p.actH + (long)bm * p.K;
        Bh = p.WTh + (long)bn * p.K;
        int region = bn / p.Nd;
        obm = bm; obn = bn - region * p.Nd; ldc = p.Nd;
        if (region == 0)      { mode = 0; Oh = p.Qh; bias = p.qb; }
        else if (region == 1) { mode = 0; Oh = p.Kh; bias = p.kb; }
        else                  { mode = 1; Of = p.hF; bias = p.sb; }
    } else {
        int tv = t - p.tilesP;
        int tm = tv >> 2, tn = tv & 3;
        int bm = tm * 128, bn = tn * 256;
        Ah = p.WTh + (long)(3 * p.Nd + bm) * p.K;
        Bh = p.actH + (long)bn * p.K;
        mode = 2; Oh = p.Vth; bias = p.vb;
        obm = bm; obn = bn; ldc = NND;
    }

    Core c;
    c.init(sb, Ah, Bh, p.K);
    c.run();

    int lane = c.lane;
    #pragma unroll
    for (int i = 0; i < 4; ++i) {
        int mlb = c.m0 + i * 16 + (lane >> 2);
        #pragma unroll
        for (int j = 0; j < 8; ++j) {
            int nl = c.n0 + j * 8 + (lane & 3) * 2;
            #pragma unroll
            for (int h = 0; h < 2; ++h) {
                int ml = mlb + h * 8;
                float v0 = c.acc[i][j][h * 2 + 0];
                float v1 = c.acc[i][j][h * 2 + 1];
                if (mode == 2) { float b = bias[obm + ml]; v0 += b; v1 += b; }
                else           { v0 += bias[obn + nl]; v1 += bias[obn + nl + 1]; }
                long idx = (long)(obm + ml) * ldc + obn + nl;
                if (mode == 1) {
                    *(float2*)(Of + idx) = make_float2(v0, v1);
                } else {
                    *(__half2*)(Oh + idx) =
                        __halves2half2(__float2half_rn(v0), __float2half_rn(v1));
                }
            }
        }
    }
}

// ---------------- scores / alphaV GEMM ----------------
struct TGP {
    const f16* Ah; int lda; long sAz;
    const f16* Bh; int ldb; long sBz;
    float* C; int ldc; long sCz;
    const float* g; int ldg;         // EPI2
    const float* w; long sWz;        // EPI2
    int K;
};

// EPI: 0 fp32 plain, 2 fp32 C+=acc+g[m]*w[n]
template<int EPI>
__global__ __launch_bounds__(256, 1) void mma_gemm(TGP p) {
    extern __shared__ char dsm[];
    uint32_t sb = cvta_smem(dsm);
    int z = blockIdx.z;
    int bm = blockIdx.y * 128, bn = blockIdx.x * 256;
    const f16* Ah = p.Ah + (long)z * p.sAz + (long)bm * p.lda;
    const f16* Bh = p.Bh + (long)z * p.sBz + (long)bn * p.ldb;

    int tid = threadIdx.x, lane = tid & 31, wid = tid >> 5;
    int m0 = (wid & 1) * 64, n0 = (wid >> 1) * 64;
    float acc[4][8][4];
    #pragma unroll
    for (int i = 0; i < 4; i++)
        #pragma unroll
        for (int j = 0; j < 8; j++)
            #pragma unroll
            for (int q = 0; q < 4; q++) acc[i][j][q] = 0.0f;

    auto load_chunk = [&](int ch, int s) {
        int k0 = ch * BK;
        uint32_t stb = sb + (uint32_t)s * STAGE_B;
        #pragma unroll
        for (int it = 0; it < 4; ++it) {
            int e = tid + it * 256;
            int r = e >> 3, c8 = (e & 7) * 8;
            const void* src = Ah + (long)r * p.lda + k0 + c8;
            uint32_t dst = stb + (uint32_t)(r * LDS + c8) * 2;
            asm volatile("cp.async.cg.shared.global [%0], [%1], 16;"
                         :: "r"(dst), "l"(src));
        }
        #pragma unroll
        for (int it = 0; it < 8; ++it) {
            int e = tid + it * 256;
            int r = e >> 3, c8 = (e & 7) * 8;
            const void* src = Bh + (long)r * p.ldb + k0 + c8;
            uint32_t dst = stb + TA_B + (uint32_t)(r * LDS + c8) * 2;
            asm volatile("cp.async.cg.shared.global [%0], [%1], 16;"
                         :: "r"(dst), "l"(src));
        }
        asm volatile("cp.async.commit_group;");
    };

    int arow = lane & 15, acol = (lane >> 4) * 8;
    int brow = (lane & 7) + ((lane >> 4) << 3);
    int bcol = ((lane >> 3) & 1) * 8;

    auto compute = [&](int s) {
        uint32_t stb = sb + (uint32_t)s * STAGE_B;
        #pragma unroll
        for (int ks = 0; ks < 4; ++ks) {
            int kk = ks * 16;
            uint32_t a[4][4];
            #pragma unroll
            for (int i = 0; i < 4; ++i)
                ldm4(stb + (uint32_t)((m0 + i * 16 + arow) * LDS + kk + acol) * 2,
                     a[i][0], a[i][1], a[i][2], a[i][3]);
            uint32_t b[8][2];
            #pragma unroll
            for (int jj = 0; jj < 4; ++jj) {
                uint32_t r0, r1, r2, r3;
                ldm4(stb + TA_B + (uint32_t)((n0 + jj * 16 + brow) * LDS + kk + bcol) * 2,
                     r0, r1, r2, r3);
                b[jj * 2][0] = r0;     b[jj * 2][1] = r1;
                b[jj * 2 + 1][0] = r2; b[jj * 2 + 1][1] = r3;
            }
            #pragma unroll
            for (int i = 0; i < 4; ++i)
                #pragma unroll
                for (int j = 0; j < 8; ++j)
                    mma16816(acc[i][j], a[i], b[j][0], b[j][1]);
        }
    };

    int nch = p.K / BK;
    load_chunk(0, 0);
    load_chunk(1, 1);
    for (int ch = 0; ch < nch; ++ch) {
        if (ch + 1 < nch) asm volatile("cp.async.wait_group 1;" ::: "memory");
        else              asm volatile("cp.async.wait_group 0;" ::: "memory");
        __syncthreads();
        if (ch + 2 < nch) load_chunk(ch + 2, (ch + 2) % NSTAGE);
        compute(ch % NSTAGE);
    }

    float* C = p.C + (long)z * p.sCz;
    #pragma unroll
    for (int i = 0; i < 4; ++i) {
        int rbase = bm + m0 + i * 16 + (lane >> 2);
        #pragma unroll
        for (int j = 0; j < 8; ++j) {
            int c = bn + n0 + j * 8 + (lane & 3) * 2;
            #pragma unroll
            for (int h = 0; h < 2; ++h) {
                int m = rbase + h * 8;
                long idx = (long)m * p.ldc + c;
                float v0 = acc[i][j][h * 2 + 0];
                float v1 = acc[i][j][h * 2 + 1];
                if constexpr (EPI == 2) {
                    float gw = p.g[(long)m * p.ldg + z];
                    const float* w = p.w + (long)z * p.sWz;
                    float2 cv = *(const float2*)(C + idx);
                    v0 += cv.x + gw * w[c];
                    v1 += cv.y + gw * w[c + 1];
                }
                *(float2*)(C + idx) = make_float2(v0, v1);
            }
        }
    }
}

// ---------------- misc kernels ----------------
__device__ __forceinline__ float bred(float v, float* sh, bool ismax) {
    int lane = threadIdx.x & 31, w = threadIdx.x >> 5;
    #pragma unroll
    for (int o = 16; o > 0; o >>= 1) {
        float t = __shfl_xor_sync(0xffffffffu, v, o);
        v = ismax ? fmaxf(v, t) : (v + t);
    }
    if (lane == 0) sh[w] = v;
    __syncthreads();
    if (w == 0) {
        int nw = blockDim.x >> 5;
        v = (lane < nw) ? sh[lane] : (ismax ? -1e30f : 0.0f);
        #pragma unroll
        for (int o = 16; o > 0; o >>= 1) {
            float t = __shfl_xor_sync(0xffffffffu, v, o);
            v = ismax ? fmaxf(v, t) : (v + t);
        }
        if (lane == 0) sh[0] = v;
    }
    __syncthreads();
    float r = sh[0];
    __syncthreads();
    return r;
}

__global__ void transpose_split_k(const float* __restrict__ X, float* __restrict__ XT,
                                  f16* __restrict__ Xh, int n) {
    __shared__ float t[32][33];
    int bx = blockIdx.x * 32, by = blockIdx.y * 32;
    int tx = threadIdx.x, ty = threadIdx.y;
    #pragma unroll
    for (int i = 0; i < 32; i += 8) {
        long o = (long)(by + ty + i) * n + bx + tx;
        float v = X[o];
        t[ty + i][tx] = v;
        Xh[o] = __float2half_rn(v);
    }
    __syncthreads();
    #pragma unroll
    for (int i = 0; i < 32; i += 8)
        XT[(long)(bx + ty + i) * n + by + tx] = t[tx][ty + i];
}

// batched weight transpose+convert: R13 inner geometry, 4 weights via blockIdx.z
struct TSP { const float* W[4]; f16* T[4]; int Kd, Nd; };

__global__ void tsplit4_k(TSP p) {
    __shared__ float t[64][33];
    const float* W = p.W[blockIdx.z];
    f16* Th = p.T[blockIdx.z];
    int n0 = blockIdx.x * 32, k0 = blockIdx.y * 64;
    int tx = threadIdx.x, ty = threadIdx.y;
    #pragma unroll
    for (int i = 0; i < 8; ++i)
        t[ty + i * 8][tx] = W[(long)(k0 + ty + i * 8) * p.Nd + n0 + tx];
    __syncthreads();
    #pragma unroll
    for (int i = 0; i < 4; ++i) {
        int nn = ty + i * 8;
        __half2 hh = __halves2half2(__float2half_rn(t[tx * 2][nn]),
                                    __float2half_rn(t[tx * 2 + 1][nn]));
        long o = (long)(n0 + nn) * p.Kd + k0 + tx * 2;
        *(__half2*)(Th + o) = hh;
    }
}

// softmax with edge term + inline qe; vectorized float4 loads; alpha f16; g[c,h]
__global__ __launch_bounds__(256) void softmax_k(const float* __restrict__ S,
                                                 const float* __restrict__ xT,
                                                 const f16* __restrict__ Qh, int ldq,
                                                 const float* __restrict__ ew,
                                                 float* __restrict__ g,
                                                 f16* __restrict__ Sh, int H) {
    int c = blockIdx.x, h = blockIdx.y;
    long off = ((long)h * NND + c) * NND;
    int tid = threadIdx.x;
    __shared__ float sh[32];

    // inline qe: qv = Q[c, h*CDD :] . We_h  (half2 x float2, 512 elems / 256 thr)
    float qv = 0.0f;
    {
        const __half2* q2 = (const __half2*)(Qh + (long)c * ldq + h * CDD);
        const float2* w2 = (const float2*)(ew + h * CDD);
        __half2 qh2 = q2[tid];
        float2 wv = w2[tid];
        qv = __half2float(__low2half(qh2)) * wv.x + __half2float(__high2half(qh2)) * wv.y;
        qv = bred(qv, sh, false);
    }

    const float scale = 0.044194173824159216f;  // 1/sqrt(512)
    float4 sv = ((const float4*)(S + off))[tid];
    float4 xv = ((const float4*)(xT + (long)c * NND))[tid];
    float l[4];
    l[0] = (sv.x + xv.x * qv) * scale;
    l[1] = (sv.y + xv.y * qv) * scale;
    l[2] = (sv.z + xv.z * qv) * scale;
    l[3] = (sv.w + xv.w * qv) * scale;
    float mx = fmaxf(fmaxf(l[0], l[1]), fmaxf(l[2], l[3]));
    mx = bred(mx, sh, true);
    float e0 = __expf(l[0] - mx), e1 = __expf(l[1] - mx);
    float e2 = __expf(l[2] - mx), e3 = __expf(l[3] - mx);
    float s = e0 + e1 + e2 + e3;
    float gn = e0 * xv.x + e1 * xv.y + e2 * xv.z + e3 * xv.w;
    s  = bred(s,  sh, false);
    gn = bred(gn, sh, false);
    float inv = 1.0f / s;
    __half2* out2 = (__half2*)(Sh + off);
    out2[tid * 2]     = __halves2half2(__float2half_rn(e0 * inv), __float2half_rn(e1 * inv));
    out2[tid * 2 + 1] = __halves2half2(__float2half_rn(e2 * inv), __float2half_rn(e3 * inv));
    if (tid == 0) g[c * H + h] = gn * inv;
}

__global__ __launch_bounds__(256) void gnstat_k(const float* __restrict__ X,
                                                const float* __restrict__ gamma,
                                                const float* __restrict__ beta,
                                                const float* __restrict__ ms,
                                                float* __restrict__ A,
                                                float* __restrict__ B, int n, int C) {
    int col = blockIdx.x * 32 + (threadIdx.x & 31);
    int rg = threadIdx.x >> 5;       // 0..7
    float s = 0.0f, s2 = 0.0f;
    int r0 = rg * (n / 8), r1 = r0 + (n / 8);
    for (int r = r0; r < r1; ++r) {
        float v = X[(long)r * C + col];
        s += v; s2 += v * v;
    }
    __shared__ float sh[2][8][32];
    sh[0][rg][threadIdx.x & 31] = s;
    sh[1][rg][threadIdx.x & 31] = s2;
    __syncthreads();
    if (threadIdx.x < 32) {
        float S = 0.0f, S2 = 0.0f;
        #pragma unroll
        for (int gi = 0; gi < 8; ++gi) { S += sh[0][gi][threadIdx.x]; S2 += sh[1][gi][threadIdx.x]; }
        int cc = blockIdx.x * 32 + threadIdx.x;
        float mu = S / n;
        float mm = ms[cc] * mu;
        float var = S2 / n - 2.0f * mm * mu + mm * mm;
        float inv = rsqrtf(var + 1e-5f);
        float ga = gamma[cc] * inv;
        A[cc] = ga;
        B[cc] = beta[cc] - ga * mm;
    }
}

__global__ __launch_bounds__(256) void gnapply_hf_k(const float* __restrict__ X,
                                                    const float* __restrict__ A,
                                                    const float* __restrict__ B,
                                                    f16* __restrict__ Hh, int C) {
    int i4 = blockIdx.x * 256 + threadIdx.x;
    float4 v = ((const float4*)X)[i4];
    int col = (i4 * 4) & (C - 1);
    float4 a = *(const float4*)(A + col);
    float4 b = *(const float4*)(B + col);
    float y0 = v.x * a.x + b.x, y1 = v.y * a.y + b.y;
    float y2 = v.z * a.z + b.z, y3 = v.w * a.w + b.w;
    ((__half2*)Hh)[i4 * 2]     = __halves2half2(__float2half_rn(y0), __float2half_rn(y1));
    ((__half2*)Hh)[i4 * 2 + 1] = __halves2half2(__float2half_rn(y2), __float2half_rn(y3));
}

__global__ __launch_bounds__(256) void gn_rownorm_k(const float* __restrict__ X,
                                                    const float* __restrict__ A,
                                                    const float* __restrict__ B,
                                                    float* __restrict__ Y, int C) {
    int row = blockIdx.x;
    const float4* x4 = (const float4*)(X + (long)row * C);
    float4* y4 = (float4*)(Y + (long)row * C);
    float4 y[4];
    float s = 0.0f;
    #pragma unroll
    for (int i = 0; i < 4; ++i) {
        int j = threadIdx.x + i * 256;
        float4 v = x4[j];
        float4 a = ((const float4*)A)[j];
        float4 b = ((const float4*)B)[j];
        y[i].x = v.x * a.x + b.x; y[i].y = v.y * a.y + b.y;
        y[i].z = v.z * a.z + b.z; y[i].w = v.w * a.w + b.w;
        s += y[i].x * y[i].x + y[i].y * y[i].y + y[i].z * y[i].z + y[i].w * y[i].w;
    }
    __shared__ float sh[32];
    s = bred(s, sh, false);
    float inv = rsqrtf(s);
    #pragma unroll
    for (int i = 0; i < 4; ++i) {
        int j = threadIdx.x + i * 256;
        float4 o;
        o.x = y[i].x * inv; o.y = y[i].y * inv;
        o.z = y[i].z * inv; o.w = y[i].w * inv;
        y4[j] = o;
    }
}

// ---------------- host ----------------
extern "C" void kernel_launch(void* const* d_in, const int* in_sizes, int n_in,
                              void* d_out, int out_size) {
    const float* x         = (const float*)d_in[0];
    const float* q1_w      = (const float*)d_in[1];
    const float* q1_b      = (const float*)d_in[2];
    const float* k1_w      = (const float*)d_in[3];
    const float* k1_b      = (const float*)d_in[4];
    const float* v1_w      = (const float*)d_in[5];
    const float* v1_b      = (const float*)d_in[6];
    const float* e1_w      = (const float*)d_in[7];
    const float* s1_w      = (const float*)d_in[8];
    const float* s1_b      = (const float*)d_in[9];
    const float* gn1_gamma = (const float*)d_in[10];
    const float* gn1_beta  = (const float*)d_in[11];
    const float* gn1_ms    = (const float*)d_in[12];
    const float* q2_w      = (const float*)d_in[13];
    const float* q2_b      = (const float*)d_in[14];
    const float* k2_w      = (const float*)d_in[15];
    const float* k2_b      = (const float*)d_in[16];
    const float* v2_w      = (const float*)d_in[17];
    const float* v2_b      = (const float*)d_in[18];
    const float* e2_w      = (const float*)d_in[19];
    const float* s2_w      = (const float*)d_in[20];
    const float* s2_b      = (const float*)d_in[21];
    const float* gn2_gamma = (const float*)d_in[22];
    const float* gn2_beta  = (const float*)d_in[23];
    const float* gn2_ms    = (const float*)d_in[24];
    float* out = (float*)d_out;

    cudaFuncSetAttribute(mma_gemm<0>, cudaFuncAttributeMaxDynamicSharedMemorySize, SMEM_TOTAL);
    cudaFuncSetAttribute(mma_gemm<2>, cudaFuncAttributeMaxDynamicSharedMemorySize, SMEM_TOTAL);
    cudaFuncSetAttribute(proj_gemm,   cudaFuncAttributeMaxDynamicSharedMemorySize, SMEM_TOTAL);

    float *xT, *S, *gg, *h1, *h2, *gna, *gnb;
    f16 *xh, *WTh, *Qh, *Kh, *Vth, *Sh, *h1h;
    cudaGetSymbolAddress((void**)&xT,  g_xT);
    cudaGetSymbolAddress((void**)&xh,  g_xh);
    cudaGetSymbolAddress((void**)&WTh, g_WTh);
    cudaGetSymbolAddress((void**)&Qh,  g_Qh);
    cudaGetSymbolAddress((void**)&Kh,  g_Kh);
    cudaGetSymbolAddress((void**)&Vth, g_Vth);
    cudaGetSymbolAddress((void**)&S,   g_S);
    cudaGetSymbolAddress((void**)&Sh,  g_Sh);
    cudaGetSymbolAddress((void**)&h1,  g_h1);
    cudaGetSymbolAddress((void**)&h1h, g_h1h);
    cudaGetSymbolAddress((void**)&h2,  g_h2);
    cudaGetSymbolAddress((void**)&gg,  g_gg);
    cudaGetSymbolAddress((void**)&gna, g_gna);
    cudaGetSymbolAddress((void**)&gnb, g_gnb);

    transpose_split_k<<<dim3(32, 32), dim3(32, 8)>>>(x, xT, xh, NND);

    // ================= layer 1 =================
    {   // batched weight transpose (Q,K,skip,V) in one launch (R13 geometry)
        long rs = (long)HR1D * NND;
        TSP t{};
        t.W[0] = q1_w; t.W[1] = k1_w; t.W[2] = s1_w; t.W[3] = v1_w;
        t.T[0] = WTh; t.T[1] = WTh + rs; t.T[2] = WTh + 2 * rs; t.T[3] = WTh + 3 * rs;
        t.Kd = NND; t.Nd = HR1D;
        tsplit4_k<<<dim3(HR1D / 32, NND / 64, 4), dim3(32, 8)>>>(t);
    }
    {   // fused Q/K/skip/Vt projections
        PJP p{};
        p.actH = xh; p.WTh = WTh;
        p.Qh = Qh; p.Kh = Kh; p.Vth = Vth; p.hF = h1;
        p.qb = q1_b; p.kb = k1_b; p.sb = s1_b; p.vb = v1_b;
        p.K = NND; p.Nd = HR1D; p.tn0 = 3 * HR1D / 256; p.tilesP = 8 * p.tn0;
        int tiles = p.tilesP + (HR1D / 128) * 4;
        proj_gemm<<<tiles, 256, SMEM_TOTAL>>>(p);
    }
    {   // scores S_h = Q_h @ K_h^T
        TGP p{}; p.Ah = Qh; p.lda = HR1D; p.sAz = CDD;
        p.Bh = Kh; p.ldb = HR1D; p.sBz = CDD;
        p.C = S; p.ldc = NND; p.sCz = (long)NND * NND; p.K = CDD;
        mma_gemm<0><<<dim3(NND / 256, NND / 128, H1D), 256, SMEM_TOTAL>>>(p);
    }
    softmax_k<<<dim3(NND, H1D), 256>>>(S, xT, Qh, HR1D, e1_w, gg, Sh, H1D);
    {   // h1 += alpha_h @ V_h + g*We
        TGP p{}; p.Ah = Sh; p.lda = NND; p.sAz = (long)NND * NND;
        p.Bh = Vth; p.ldb = NND; p.sBz = (long)CDD * NND;
        p.C = h1; p.ldc = HR1D; p.sCz = CDD;
        p.g = gg; p.ldg = H1D; p.w = e1_w; p.sWz = CDD; p.K = NND;
        mma_gemm<2><<<dim3(CDD / 256, NND / 128, H1D), 256, SMEM_TOTAL>>>(p);
    }
    gnstat_k<<<HR1D / 32, 256>>>(h1, gn1_gamma, gn1_beta, gn1_ms, gna, gnb, NND, HR1D);
    gnapply_hf_k<<<(NND * HR1D / 4) / 256, 256>>>(h1, gna, gnb, h1h, HR1D);

    // ================= layer 2 =================
    {
        long rs = (long)HR2D * HR1D;
        TSP t{};
        t.W[0] = q2_w; t.W[1] = k2_w; t.W[2] = s2_w; t.W[3] = v2_w;
        t.T[0] = WTh; t.T[1] = WTh + rs; t.T[2] = WTh + 2 * rs; t.T[3] = WTh + 3 * rs;
        t.Kd = HR1D; t.Nd = HR2D;
        tsplit4_k<<<dim3(HR2D / 32, HR1D / 64, 4), dim3(32, 8)>>>(t);
    }
    {   // fused Q/K/skip/Vt projections
        PJP p{};
        p.actH = h1h; p.WTh = WTh;
        p.Qh = Qh; p.Kh = Kh; p.Vth = Vth; p.hF = h2;
        p.qb = q2_b; p.kb = k2_b; p.sb = s2_b; p.vb = v2_b;
        p.K = HR1D; p.Nd = HR2D; p.tn0 = 3 * HR2D / 256; p.tilesP = 8 * p.tn0;
        int tiles = p.tilesP + (HR2D / 128) * 4;
        proj_gemm<<<tiles, 256, SMEM_TOTAL>>>(p);
    }
    {   // scores
        TGP p{}; p.Ah = Qh; p.lda = HR2D; p.sAz = CDD;
        p.Bh = Kh; p.ldb = HR2D; p.sBz = CDD;
        p.C = S; p.ldc = NND; p.sCz = (long)NND * NND; p.K = CDD;
        mma_gemm<0><<<dim3(NND / 256, NND / 128, H2D), 256, SMEM_TOTAL>>>(p);
    }
    softmax_k<<<dim3(NND, H2D), 256>>>(S, xT, Qh, HR2D, e2_w, gg, Sh, H2D);
    {   // h2 += alpha @ V + g*We
        TGP p{}; p.Ah = Sh; p.lda = NND; p.sAz = (long)NND * NND;
        p.Bh = Vth; p.ldb = NND; p.sBz = (long)CDD * NND;
        p.C = h2; p.ldc = HR2D; p.sCz = CDD;
        p.g = gg; p.ldg = H2D; p.w = e2_w; p.sWz = CDD; p.K = NND;
        mma_gemm<2><<<dim3(CDD / 256, NND / 128, H2D), 256, SMEM_TOTAL>>>(p);
    }

    gnstat_k<<<HR2D / 32, 256>>>(h2, gn2_gamma, gn2_beta, gn2_ms, gna, gnb, NND, HR2D);
    gn_rownorm_k<<<NND, 256>>>(h2, gna, gnb, out, HR2D);
}

// round 17
// speedup vs baseline: 1.0916x; 1.0916x over previous
#include <cuda_runtime.h>
#include <cuda_fp16.h>
#include <math.h>
#include <stdint.h>

typedef __half f16;

// Problem dims (fixed)
#define NND   1024
#define HR1D  2048
#define HR2D  4096
#define H1D   4
#define H2D   8
#define CDD   512

// GEMM tiling: CTA 128(M) x 256(N), BK=64, single-pass fp16, 8 warps of 64x64
#define BK    64
#define LDS   72                       // smem row stride in f16 (padded)
#define TA_B  (128 * LDS * 2)          // 18432
#define TB_B  (256 * LDS * 2)          // 36864
#define STAGE_B (TA_B + TB_B)          // 55296
#define NSTAGE 3
#define SMEM_TOTAL (NSTAGE * STAGE_B)  // 165888

// ---------------- scratch ----------------
__device__ float g_xT [NND * NND];
__device__ f16   g_xh [NND * NND];
__device__ f16   g_WTh[4 * HR2D * HR1D];
__device__ f16   g_Qh [NND * HR2D];
__device__ f16   g_Kh [NND * HR2D];
__device__ f16   g_Vth[HR2D * NND];
__device__ float g_S  [H2D * NND * NND];
__device__ f16   g_Sh [H2D * NND * NND];
__device__ float g_h1 [NND * HR1D];
__device__ f16   g_h1h[NND * HR1D];
__device__ float g_h2 [NND * HR2D];
__device__ float g_gg [NND * H2D];
__device__ float g_gna[HR2D];
__device__ float g_gnb[HR2D];

// ---------------- helpers ----------------
__device__ __forceinline__ uint32_t cvta_smem(const void* p) {
    uint32_t a;
    asm("{ .reg .u64 t; cvta.to.shared.u64 t, %1; cvt.u32.u64 %0, t; }" : "=r"(a) : "l"(p));
    return a;
}

__device__ __forceinline__ void ldm4(uint32_t addr, uint32_t& r0, uint32_t& r1,
                                     uint32_t& r2, uint32_t& r3) {
    asm volatile("ldmatrix.sync.aligned.m8n8.x4.shared.b16 {%0,%1,%2,%3}, [%4];"
                 : "=r"(r0), "=r"(r1), "=r"(r2), "=r"(r3) : "r"(addr));
}

__device__ __forceinline__ void mma16816(float* c, const uint32_t* a,
                                         uint32_t b0, uint32_t b1) {
    asm volatile(
        "mma.sync.aligned.m16n8k16.row.col.f32.f16.f16.f32 "
        "{%0,%1,%2,%3}, {%4,%5,%6,%7}, {%8,%9}, {%0,%1,%2,%3};"
        : "+f"(c[0]), "+f"(c[1]), "+f"(c[2]), "+f"(c[3])
        : "r"(a[0]), "r"(a[1]), "r"(a[2]), "r"(a[3]), "r"(b0), "r"(b1));
}

// shared GEMM core (row stride = K for both operands), single-pass fp16,
// CTA 128x256, 8 warps of 64x64.
struct Core {
    uint32_t sb;
    const f16 *Ah, *Bh;
    int K;
    int tid, lane, wid, m0, n0;
    float acc[4][8][4];

    __device__ __forceinline__ void init(uint32_t sb_, const f16* Ah_,
                                         const f16* Bh_, int K_) {
        sb = sb_; Ah = Ah_; Bh = Bh_; K = K_;
        tid = threadIdx.x; lane = tid & 31; wid = tid >> 5;
        m0 = (wid & 1) * 64; n0 = (wid >> 1) * 64;
        #pragma unroll
        for (int i = 0; i < 4; i++)
            #pragma unroll
            for (int j = 0; j < 8; j++)
                #pragma unroll
                for (int q = 0; q < 4; q++) acc[i][j][q] = 0.0f;
    }

    __device__ __forceinline__ void load_chunk(int ch, int s) {
        int k0 = ch * BK;
        uint32_t stb = sb + (uint32_t)s * STAGE_B;
        #pragma unroll
        for (int it = 0; it < 4; ++it) {
            int e = tid + it * 256;
            int r = e >> 3, c8 = (e & 7) * 8;
            const void* src = Ah + (long)r * K + k0 + c8;
            uint32_t dst = stb + (uint32_t)(r * LDS + c8) * 2;
            asm volatile("cp.async.cg.shared.global [%0], [%1], 16;"
                         :: "r"(dst), "l"(src));
        }
        #pragma unroll
        for (int it = 0; it < 8; ++it) {
            int e = tid + it * 256;
            int r = e >> 3, c8 = (e & 7) * 8;
            const void* src = Bh + (long)r * K + k0 + c8;
            uint32_t dst = stb + TA_B + (uint32_t)(r * LDS + c8) * 2;
            asm volatile("cp.async.cg.shared.global [%0], [%1], 16;"
                         :: "r"(dst), "l"(src));
        }
        asm volatile("cp.async.commit_group;");
    }

    __device__ __forceinline__ void compute(int s) {
        int arow = lane & 15, acol = (lane >> 4) * 8;
        int brow = (lane & 7) + ((lane >> 4) << 3);
        int bcol = ((lane >> 3) & 1) * 8;
        uint32_t stb = sb + (uint32_t)s * STAGE_B;
        #pragma unroll
        for (int ks = 0; ks < 4; ++ks) {
            int kk = ks * 16;
            uint32_t a[4][4];
            #pragma unroll
            for (int i = 0; i < 4; ++i)
                ldm4(stb + (uint32_t)((m0 + i * 16 + arow) * LDS + kk + acol) * 2,
                     a[i][0], a[i][1], a[i][2], a[i][3]);
            uint32_t b[8][2];
            #pragma unroll
            for (int jj = 0; jj < 4; ++jj) {
                uint32_t r0, r1, r2, r3;
                ldm4(stb + TA_B + (uint32_t)((n0 + jj * 16 + brow) * LDS + kk + bcol) * 2,
                     r0, r1, r2, r3);
                b[jj * 2][0] = r0;     b[jj * 2][1] = r1;
                b[jj * 2 + 1][0] = r2; b[jj * 2 + 1][1] = r3;
            }
            #pragma unroll
            for (int i = 0; i < 4; ++i)
                #pragma unroll
                for (int j = 0; j < 8; ++j)
                    mma16816(acc[i][j], a[i], b[j][0], b[j][1]);
        }
    }

    __device__ __forceinline__ void run() {
        int nch = K / BK;
        load_chunk(0, 0);
        load_chunk(1, 1);
        for (int ch = 0; ch < nch; ++ch) {
            if (ch + 1 < nch) asm volatile("cp.async.wait_group 1;" ::: "memory");
            else              asm volatile("cp.async.wait_group 0;" ::: "memory");
            __syncthreads();
            if (ch + 2 < nch) load_chunk(ch + 2, (ch + 2) % NSTAGE);
            compute(ch % NSTAGE);
        }
    }
};

// ---------------- fused multi-GEMM projection kernel ----------------
struct PJP {
    const f16* actH;           // [1024 x K]
    const f16* WTh;            // [4*Nd x K]
    f16 *Qh, *Kh, *Vth;
    float* hF;                 // skip fp32 [1024 x Nd]
    const float *qb, *kb, *sb, *vb;
    int K, Nd, tn0, tilesP;    // tn0 = 3*Nd/256, tilesP = 8*tn0
};

__global__ __launch_bounds__(256, 1) void proj_gemm(PJP p) {
    extern __shared__ char dsm[];
    uint32_t sb = cvta_smem(dsm);
    int t = blockIdx.x;

    const f16 *Ah, *Bh;
    f16* Oh = nullptr;
    float* Of = nullptr;
    const float* bias;
    int mode, obm, obn, ldc;
    if (t < p.tilesP) {
        int tm = t / p.tn0, tn = t % p.tn0;
        int bm = tm * 128, bn = tn * 256;
        Ah = p.actH + (long)bm * p.K;
        Bh = p.WTh + (long)bn * p.K;
        int region = bn / p.Nd;
        obm = bm; obn = bn - region * p.Nd; ldc = p.Nd;
        if (region == 0)      { mode = 0; Oh = p.Qh; bias = p.qb; }
        else if (region == 1) { mode = 0; Oh = p.Kh; bias = p.kb; }
        else                  { mode = 1; Of = p.hF; bias = p.sb; }
    } else {
        int tv = t - p.tilesP;
        int tm = tv >> 2, tn = tv & 3;
        int bm = tm * 128, bn = tn * 256;
        Ah = p.WTh + (long)(3 * p.Nd + bm) * p.K;
        Bh = p.actH + (long)bn * p.K;
        mode = 2; Oh = p.Vth; bias = p.vb;
        obm = bm; obn = bn; ldc = NND;
    }

    Core c;
    c.init(sb, Ah, Bh, p.K);
    c.run();

    int lane = c.lane;
    #pragma unroll
    for (int i = 0; i < 4; ++i) {
        int mlb = c.m0 + i * 16 + (lane >> 2);
        #pragma unroll
        for (int j = 0; j < 8; ++j) {
            int nl = c.n0 + j * 8 + (lane & 3) * 2;
            #pragma unroll
            for (int h = 0; h < 2; ++h) {
                int ml = mlb + h * 8;
                float v0 = c.acc[i][j][h * 2 + 0];
                float v1 = c.acc[i][j][h * 2 + 1];
                if (mode == 2) { float b = bias[obm + ml]; v0 += b; v1 += b; }
                else           { v0 += bias[obn + nl]; v1 += bias[obn + nl + 1]; }
                long idx = (long)(obm + ml) * ldc + obn + nl;
                if (mode == 1) {
                    *(float2*)(Of + idx) = make_float2(v0, v1);
                } else {
                    *(__half2*)(Oh + idx) =
                        __halves2half2(__float2half_rn(v0), __float2half_rn(v1));
                }
            }
        }
    }
}

// ---------------- scores / alphaV GEMM ----------------
struct TGP {
    const f16* Ah; int lda; long sAz;
    const f16* Bh; int ldb; long sBz;
    float* C; int ldc; long sCz;
    const float* g; int ldg;         // EPI2
    const float* w; long sWz;        // EPI2
    int K;
};

// EPI: 0 fp32 plain, 2 fp32 C+=acc+g[m]*w[n]
template<int EPI>
__global__ __launch_bounds__(256, 1) void mma_gemm(TGP p) {
    extern __shared__ char dsm[];
    uint32_t sb = cvta_smem(dsm);
    int z = blockIdx.z;
    int bm = blockIdx.y * 128, bn = blockIdx.x * 256;
    const f16* Ah = p.Ah + (long)z * p.sAz + (long)bm * p.lda;
    const f16* Bh = p.Bh + (long)z * p.sBz + (long)bn * p.ldb;

    int tid = threadIdx.x, lane = tid & 31, wid = tid >> 5;
    int m0 = (wid & 1) * 64, n0 = (wid >> 1) * 64;
    float acc[4][8][4];
    #pragma unroll
    for (int i = 0; i < 4; i++)
        #pragma unroll
        for (int j = 0; j < 8; j++)
            #pragma unroll
            for (int q = 0; q < 4; q++) acc[i][j][q] = 0.0f;

    auto load_chunk = [&](int ch, int s) {
        int k0 = ch * BK;
        uint32_t stb = sb + (uint32_t)s * STAGE_B;
        #pragma unroll
        for (int it = 0; it < 4; ++it) {
            int e = tid + it * 256;
            int r = e >> 3, c8 = (e & 7) * 8;
            const void* src = Ah + (long)r * p.lda + k0 + c8;
            uint32_t dst = stb + (uint32_t)(r * LDS + c8) * 2;
            asm volatile("cp.async.cg.shared.global [%0], [%1], 16;"
                         :: "r"(dst), "l"(src));
        }
        #pragma unroll
        for (int it = 0; it < 8; ++it) {
            int e = tid + it * 256;
            int r = e >> 3, c8 = (e & 7) * 8;
            const void* src = Bh + (long)r * p.ldb + k0 + c8;
            uint32_t dst = stb + TA_B + (uint32_t)(r * LDS + c8) * 2;
            asm volatile("cp.async.cg.shared.global [%0], [%1], 16;"
                         :: "r"(dst), "l"(src));
        }
        asm volatile("cp.async.commit_group;");
    };

    int arow = lane & 15, acol = (lane >> 4) * 8;
    int brow = (lane & 7) + ((lane >> 4) << 3);
    int bcol = ((lane >> 3) & 1) * 8;

    auto compute = [&](int s) {
        uint32_t stb = sb + (uint32_t)s * STAGE_B;
        #pragma unroll
        for (int ks = 0; ks < 4; ++ks) {
            int kk = ks * 16;
            uint32_t a[4][4];
            #pragma unroll
            for (int i = 0; i < 4; ++i)
                ldm4(stb + (uint32_t)((m0 + i * 16 + arow) * LDS + kk + acol) * 2,
                     a[i][0], a[i][1], a[i][2], a[i][3]);
            uint32_t b[8][2];
            #pragma unroll
            for (int jj = 0; jj < 4; ++jj) {
                uint32_t r0, r1, r2, r3;
                ldm4(stb + TA_B + (uint32_t)((n0 + jj * 16 + brow) * LDS + kk + bcol) * 2,
                     r0, r1, r2, r3);
                b[jj * 2][0] = r0;     b[jj * 2][1] = r1;
                b[jj * 2 + 1][0] = r2; b[jj * 2 + 1][1] = r3;
            }
            #pragma unroll
            for (int i = 0; i < 4; ++i)
                #pragma unroll
                for (int j = 0; j < 8; ++j)
                    mma16816(acc[i][j], a[i], b[j][0], b[j][1]);
        }
    };

    int nch = p.K / BK;
    load_chunk(0, 0);
    load_chunk(1, 1);
    for (int ch = 0; ch < nch; ++ch) {
        if (ch + 1 < nch) asm volatile("cp.async.wait_group 1;" ::: "memory");
        else              asm volatile("cp.async.wait_group 0;" ::: "memory");
        __syncthreads();
        if (ch + 2 < nch) load_chunk(ch + 2, (ch + 2) % NSTAGE);
        compute(ch % NSTAGE);
    }

    float* C = p.C + (long)z * p.sCz;
    #pragma unroll
    for (int i = 0; i < 4; ++i) {
        int rbase = bm + m0 + i * 16 + (lane >> 2);
        #pragma unroll
        for (int j = 0; j < 8; ++j) {
            int c = bn + n0 + j * 8 + (lane & 3) * 2;
            #pragma unroll
            for (int h = 0; h < 2; ++h) {
                int m = rbase + h * 8;
                long idx = (long)m * p.ldc + c;
                float v0 = acc[i][j][h * 2 + 0];
                float v1 = acc[i][j][h * 2 + 1];
                if constexpr (EPI == 2) {
                    float gw = p.g[(long)m * p.ldg + z];
                    const float* w = p.w + (long)z * p.sWz;
                    float2 cv = *(const float2*)(C + idx);
                    v0 += cv.x + gw * w[c];
                    v1 += cv.y + gw * w[c + 1];
                }
                *(float2*)(C + idx) = make_float2(v0, v1);
            }
        }
    }
}

// ---------------- misc kernels ----------------
__device__ __forceinline__ float bred(float v, float* sh, bool ismax) {
    int lane = threadIdx.x & 31, w = threadIdx.x >> 5;
    #pragma unroll
    for (int o = 16; o > 0; o >>= 1) {
        float t = __shfl_xor_sync(0xffffffffu, v, o);
        v = ismax ? fmaxf(v, t) : (v + t);
    }
    if (lane == 0) sh[w] = v;
    __syncthreads();
    if (w == 0) {
        int nw = blockDim.x >> 5;
        v = (lane < nw) ? sh[lane] : (ismax ? -1e30f : 0.0f);
        #pragma unroll
        for (int o = 16; o > 0; o >>= 1) {
            float t = __shfl_xor_sync(0xffffffffu, v, o);
            v = ismax ? fmaxf(v, t) : (v + t);
        }
        if (lane == 0) sh[0] = v;
    }
    __syncthreads();
    float r = sh[0];
    __syncthreads();
    return r;
}

__global__ void transpose_split_k(const float* __restrict__ X, float* __restrict__ XT,
                                  f16* __restrict__ Xh, int n) {
    __shared__ float t[32][33];
    int bx = blockIdx.x * 32, by = blockIdx.y * 32;
    int tx = threadIdx.x, ty = threadIdx.y;
    #pragma unroll
    for (int i = 0; i < 32; i += 8) {
        long o = (long)(by + ty + i) * n + bx + tx;
        float v = X[o];
        t[ty + i][tx] = v;
        Xh[o] = __float2half_rn(v);
    }
    __syncthreads();
    #pragma unroll
    for (int i = 0; i < 32; i += 8)
        XT[(long)(bx + ty + i) * n + by + tx] = t[tx][ty + i];
}

// weight transpose+convert (R13/R15 proven version, separate launches)
__global__ void tsplit_k(const float* __restrict__ W, f16* __restrict__ Th,
                         int Kd, int Nd) {
    __shared__ float t[64][33];
    int n0 = blockIdx.x * 32, k0 = blockIdx.y * 64;
    int tx = threadIdx.x, ty = threadIdx.y;
    #pragma unroll
    for (int i = 0; i < 8; ++i)
        t[ty + i * 8][tx] = W[(long)(k0 + ty + i * 8) * Nd + n0 + tx];
    __syncthreads();
    #pragma unroll
    for (int i = 0; i < 4; ++i) {
        int nn = ty + i * 8;
        __half2 hh = __halves2half2(__float2half_rn(t[tx * 2][nn]),
                                    __float2half_rn(t[tx * 2 + 1][nn]));
        long o = (long)(n0 + nn) * Kd + k0 + tx * 2;
        *(__half2*)(Th + o) = hh;
    }
}

// softmax with edge term + inline qe; vectorized float4 loads; alpha f16; g[c,h]
__global__ __launch_bounds__(256) void softmax_k(const float* __restrict__ S,
                                                 const float* __restrict__ xT,
                                                 const f16* __restrict__ Qh, int ldq,
                                                 const float* __restrict__ ew,
                                                 float* __restrict__ g,
                                                 f16* __restrict__ Sh, int H) {
    int c = blockIdx.x, h = blockIdx.y;
    long off = ((long)h * NND + c) * NND;
    int tid = threadIdx.x;
    __shared__ float sh[32];

    // inline qe: qv = Q[c, h*CDD :] . We_h  (half2 x float2, 512 elems / 256 thr)
    float qv = 0.0f;
    {
        const __half2* q2 = (const __half2*)(Qh + (long)c * ldq + h * CDD);
        const float2* w2 = (const float2*)(ew + h * CDD);
        __half2 qh2 = q2[tid];
        float2 wv = w2[tid];
        qv = __half2float(__low2half(qh2)) * wv.x + __half2float(__high2half(qh2)) * wv.y;
        qv = bred(qv, sh, false);
    }

    const float scale = 0.044194173824159216f;  // 1/sqrt(512)
    float4 sv = ((const float4*)(S + off))[tid];
    float4 xv = ((const float4*)(xT + (long)c * NND))[tid];
    float l[4];
    l[0] = (sv.x + xv.x * qv) * scale;
    l[1] = (sv.y + xv.y * qv) * scale;
    l[2] = (sv.z + xv.z * qv) * scale;
    l[3] = (sv.w + xv.w * qv) * scale;
    float mx = fmaxf(fmaxf(l[0], l[1]), fmaxf(l[2], l[3]));
    mx = bred(mx, sh, true);
    float e0 = __expf(l[0] - mx), e1 = __expf(l[1] - mx);
    float e2 = __expf(l[2] - mx), e3 = __expf(l[3] - mx);
    float s = e0 + e1 + e2 + e3;
    float gn = e0 * xv.x + e1 * xv.y + e2 * xv.z + e3 * xv.w;
    s  = bred(s,  sh, false);
    gn = bred(gn, sh, false);
    float inv = 1.0f / s;
    __half2* out2 = (__half2*)(Sh + off);
    out2[tid * 2]     = __halves2half2(__float2half_rn(e0 * inv), __float2half_rn(e1 * inv));
    out2[tid * 2 + 1] = __halves2half2(__float2half_rn(e2 * inv), __float2half_rn(e3 * inv));
    if (tid == 0) g[c * H + h] = gn * inv;
}

__global__ __launch_bounds__(256) void gnstat_k(const float* __restrict__ X,
                                                const float* __restrict__ gamma,
                                                const float* __restrict__ beta,
                                                const float* __restrict__ ms,
                                                float* __restrict__ A,
                                                float* __restrict__ B, int n, int C) {
    int col = blockIdx.x * 32 + (threadIdx.x & 31);
    int rg = threadIdx.x >> 5;       // 0..7
    float s = 0.0f, s2 = 0.0f;
    int r0 = rg * (n / 8), r1 = r0 + (n / 8);
    for (int r = r0; r < r1; ++r) {
        float v = X[(long)r * C + col];
        s += v; s2 += v * v;
    }
    __shared__ float sh[2][8][32];
    sh[0][rg][threadIdx.x & 31] = s;
    sh[1][rg][threadIdx.x & 31] = s2;
    __syncthreads();
    if (threadIdx.x < 32) {
        float S = 0.0f, S2 = 0.0f;
        #pragma unroll
        for (int gi = 0; gi < 8; ++gi) { S += sh[0][gi][threadIdx.x]; S2 += sh[1][gi][threadIdx.x]; }
        int cc = blockIdx.x * 32 + threadIdx.x;
        float mu = S / n;
        float mm = ms[cc] * mu;
        float var = S2 / n - 2.0f * mm * mu + mm * mm;
        float inv = rsqrtf(var + 1e-5f);
        float ga = gamma[cc] * inv;
        A[cc] = ga;
        B[cc] = beta[cc] - ga * mm;
    }
}

__global__ __launch_bounds__(256) void gnapply_hf_k(const float* __restrict__ X,
                                                    const float* __restrict__ A,
                                                    const float* __restrict__ B,
                                                    f16* __restrict__ Hh, int C) {
    int i4 = blockIdx.x * 256 + threadIdx.x;
    float4 v = ((const float4*)X)[i4];
    int col = (i4 * 4) & (C - 1);
    float4 a = *(const float4*)(A + col);
    float4 b = *(const float4*)(B + col);
    float y0 = v.x * a.x + b.x, y1 = v.y * a.y + b.y;
    float y2 = v.z * a.z + b.z, y3 = v.w * a.w + b.w;
    ((__half2*)Hh)[i4 * 2]     = __halves2half2(__float2half_rn(y0), __float2half_rn(y1));
    ((__half2*)Hh)[i4 * 2 + 1] = __halves2half2(__float2half_rn(y2), __float2half_rn(y3));
}

__global__ __launch_bounds__(256) void gn_rownorm_k(const float* __restrict__ X,
                                                    const float* __restrict__ A,
                                                    const float* __restrict__ B,
                                                    float* __restrict__ Y, int C) {
    int row = blockIdx.x;
    const float4* x4 = (const float4*)(X + (long)row * C);
    float4* y4 = (float4*)(Y + (long)row * C);
    float4 y[4];
    float s = 0.0f;
    #pragma unroll
    for (int i = 0; i < 4; ++i) {
        int j = threadIdx.x + i * 256;
        float4 v = x4[j];
        float4 a = ((const float4*)A)[j];
        float4 b = ((const float4*)B)[j];
        y[i].x = v.x * a.x + b.x; y[i].y = v.y * a.y + b.y;
        y[i].z = v.z * a.z + b.z; y[i].w = v.w * a.w + b.w;
        s += y[i].x * y[i].x + y[i].y * y[i].y + y[i].z * y[i].z + y[i].w * y[i].w;
    }
    __shared__ float sh[32];
    s = bred(s, sh, false);
    float inv = rsqrtf(s);
    #pragma unroll
    for (int i = 0; i < 4; ++i) {
        int j = threadIdx.x + i * 256;
        float4 o;
        o.x = y[i].x * inv; o.y = y[i].y * inv;
        o.z = y[i].z * inv; o.w = y[i].w * inv;
        y4[j] = o;
    }
}

// ---------------- host ----------------
extern "C" void kernel_launch(void* const* d_in, const int* in_sizes, int n_in,
                              void* d_out, int out_size) {
    const float* x         = (const float*)d_in[0];
    const float* q1_w      = (const float*)d_in[1];
    const float* q1_b      = (const float*)d_in[2];
    const float* k1_w      = (const float*)d_in[3];
    const float* k1_b      = (const float*)d_in[4];
    const float* v1_w      = (const float*)d_in[5];
    const float* v1_b      = (const float*)d_in[6];
    const float* e1_w      = (const float*)d_in[7];
    const float* s1_w      = (const float*)d_in[8];
    const float* s1_b      = (const float*)d_in[9];
    const float* gn1_gamma = (const float*)d_in[10];
    const float* gn1_beta  = (const float*)d_in[11];
    const float* gn1_ms    = (const float*)d_in[12];
    const float* q2_w      = (const float*)d_in[13];
    const float* q2_b      = (const float*)d_in[14];
    const float* k2_w      = (const float*)d_in[15];
    const float* k2_b      = (const float*)d_in[16];
    const float* v2_w      = (const float*)d_in[17];
    const float* v2_b      = (const float*)d_in[18];
    const float* e2_w      = (const float*)d_in[19];
    const float* s2_w      = (const float*)d_in[20];
    const float* s2_b      = (const float*)d_in[21];
    const float* gn2_gamma = (const float*)d_in[22];
    const float* gn2_beta  = (const float*)d_in[23];
    const float* gn2_ms    = (const float*)d_in[24];
    float* out = (float*)d_out;

    cudaFuncSetAttribute(mma_gemm<0>, cudaFuncAttributeMaxDynamicSharedMemorySize, SMEM_TOTAL);
    cudaFuncSetAttribute(mma_gemm<2>, cudaFuncAttributeMaxDynamicSharedMemorySize, SMEM_TOTAL);
    cudaFuncSetAttribute(proj_gemm,   cudaFuncAttributeMaxDynamicSharedMemorySize, SMEM_TOTAL);

    float *xT, *S, *gg, *h1, *h2, *gna, *gnb;
    f16 *xh, *WTh, *Qh, *Kh, *Vth, *Sh, *h1h;
    cudaGetSymbolAddress((void**)&xT,  g_xT);
    cudaGetSymbolAddress((void**)&xh,  g_xh);
    cudaGetSymbolAddress((void**)&WTh, g_WTh);
    cudaGetSymbolAddress((void**)&Qh,  g_Qh);
    cudaGetSymbolAddress((void**)&Kh,  g_Kh);
    cudaGetSymbolAddress((void**)&Vth, g_Vth);
    cudaGetSymbolAddress((void**)&S,   g_S);
    cudaGetSymbolAddress((void**)&Sh,  g_Sh);
    cudaGetSymbolAddress((void**)&h1,  g_h1);
    cudaGetSymbolAddress((void**)&h1h, g_h1h);
    cudaGetSymbolAddress((void**)&h2,  g_h2);
    cudaGetSymbolAddress((void**)&gg,  g_gg);
    cudaGetSymbolAddress((void**)&gna, g_gna);
    cudaGetSymbolAddress((void**)&gnb, g_gnb);

    transpose_split_k<<<dim3(32, 32), dim3(32, 8)>>>(x, xT, xh, NND);

    // ================= layer 1 =================
    {
        long rs = (long)HR1D * NND;
        tsplit_k<<<dim3(HR1D / 32, NND / 64), dim3(32, 8)>>>(q1_w, WTh,          NND, HR1D);
        tsplit_k<<<dim3(HR1D / 32, NND / 64), dim3(32, 8)>>>(k1_w, WTh + rs,     NND, HR1D);
        tsplit_k<<<dim3(HR1D / 32, NND / 64), dim3(32, 8)>>>(s1_w, WTh + 2 * rs, NND, HR1D);
        tsplit_k<<<dim3(HR1D / 32, NND / 64), dim3(32, 8)>>>(v1_w, WTh + 3 * rs, NND, HR1D);
    }
    {   // fused Q/K/skip/Vt projections
        PJP p{};
        p.actH = xh; p.WTh = WTh;
        p.Qh = Qh; p.Kh = Kh; p.Vth = Vth; p.hF = h1;
        p.qb = q1_b; p.kb = k1_b; p.sb = s1_b; p.vb = v1_b;
        p.K = NND; p.Nd = HR1D; p.tn0 = 3 * HR1D / 256; p.tilesP = 8 * p.tn0;
        int tiles = p.tilesP + (HR1D / 128) * 4;
        proj_gemm<<<tiles, 256, SMEM_TOTAL>>>(p);
    }
    {   // scores S_h = Q_h @ K_h^T
        TGP p{}; p.Ah = Qh; p.lda = HR1D; p.sAz = CDD;
        p.Bh = Kh; p.ldb = HR1D; p.sBz = CDD;
        p.C = S; p.ldc = NND; p.sCz = (long)NND * NND; p.K = CDD;
        mma_gemm<0><<<dim3(NND / 256, NND / 128, H1D), 256, SMEM_TOTAL>>>(p);
    }
    softmax_k<<<dim3(NND, H1D), 256>>>(S, xT, Qh, HR1D, e1_w, gg, Sh, H1D);
    {   // h1 += alpha_h @ V_h + g*We
        TGP p{}; p.Ah = Sh; p.lda = NND; p.sAz = (long)NND * NND;
        p.Bh = Vth; p.ldb = NND; p.sBz = (long)CDD * NND;
        p.C = h1; p.ldc = HR1D; p.sCz = CDD;
        p.g = gg; p.ldg = H1D; p.w = e1_w; p.sWz = CDD; p.K = NND;
        mma_gemm<2><<<dim3(CDD / 256, NND / 128, H1D), 256, SMEM_TOTAL>>>(p);
    }
    gnstat_k<<<HR1D / 32, 256>>>(h1, gn1_gamma, gn1_beta, gn1_ms, gna, gnb, NND, HR1D);
    gnapply_hf_k<<<(NND * HR1D / 4) / 256, 256>>>(h1, gna, gnb, h1h, HR1D);

    // ================= layer 2 =================
    {
        long rs = (long)HR2D * HR1D;
        tsplit_k<<<dim3(HR2D / 32, HR1D / 64), dim3(32, 8)>>>(q2_w, WTh,          HR1D, HR2D);
        tsplit_k<<<dim3(HR2D / 32, HR1D / 64), dim3(32, 8)>>>(k2_w, WTh + rs,     HR1D, HR2D);
        tsplit_k<<<dim3(HR2D / 32, HR1D / 64), dim3(32, 8)>>>(s2_w, WTh + 2 * rs, HR1D, HR2D);
        tsplit_k<<<dim3(HR2D / 32, HR1D / 64), dim3(32, 8)>>>(v2_w, WTh + 3 * rs, HR1D, HR2D);
    }
    {   // fused Q/K/skip/Vt projections
        PJP p{};
        p.actH = h1h; p.WTh = WTh;
        p.Qh = Qh; p.Kh = Kh; p.Vth = Vth; p.hF = h2;
        p.qb = q2_b; p.kb = k2_b; p.sb = s2_b; p.vb = v2_b;
        p.K = HR1D; p.Nd = HR2D; p.tn0 = 3 * HR2D / 256; p.tilesP = 8 * p.tn0;
        int tiles = p.tilesP + (HR2D / 128) * 4;
        proj_gemm<<<tiles, 256, SMEM_TOTAL>>>(p);
    }
    {   // scores
        TGP p{}; p.Ah = Qh; p.lda = HR2D; p.sAz = CDD;
        p.Bh = Kh; p.ldb = HR2D; p.sBz = CDD;
        p.C = S; p.ldc = NND; p.sCz = (long)NND * NND; p.K = CDD;
        mma_gemm<0><<<dim3(NND / 256, NND / 128, H2D), 256, SMEM_TOTAL>>>(p);
    }
    softmax_k<<<dim3(NND, H2D), 256>>>(S, xT, Qh, HR2D, e2_w, gg, Sh, H2D);
    {   // h2 += alpha @ V + g*We
        TGP p{}; p.Ah = Sh; p.lda = NND; p.sAz = (long)NND * NND;
        p.Bh = Vth; p.ldb = NND; p.sBz = (long)CDD * NND;
        p.C = h2; p.ldc = HR2D; p.sCz = CDD;
        p.g = gg; p.ldg = H2D; p.w = e2_w; p.sWz = CDD; p.K = NND;
        mma_gemm<2><<<dim3(CDD / 256, NND / 128, H2D), 256, SMEM_TOTAL>>>(p);
    }

    gnstat_k<<<HR2D / 32, 256>>>(h2, gn2_gamma, gn2_beta, gn2_ms, gna, gnb, NND, HR2D);
    gn_rownorm_k<<<NND, 256>>>(h2, gna, gnb, out, HR2D);
}